// round 11
// baseline (speedup 1.0000x reference)
#include <cuda_runtime.h>
#include <cuda_fp16.h>
#include <cstdint>

#define B_   4
#define T_   4096
#define I_   1024
#define H_   16
#define D_   64
#define M_   (B_ * T_)        // 16384 rows (b,t)
#define NTOT 2048             // total N columns = H * 128
#define CH   64               // scan chunk length
#define NC   (T_ / CH)        // 64 chunks
#define NBH  (B_ * H_)        // 64 (b,h) pairs

#define KC   32               // K per pipeline stage
#define NST  (I_ / KC)        // 32 stages
#define STG  4                // ring depth

// ---------------- scratch (device globals: allocation-free) ----------------
__device__ __align__(16) __half g_a [(size_t)M_ * I_];   // 32 MB  A fp16
__device__ __align__(16) __half g_b [(size_t)I_ * NTOT]; // 4 MB   B [K][N] fp16
__device__ __align__(16) __half g_v [ (size_t)M_ * H_ * D_ ]; // 32 MB v fp16
__device__ __align__(16) float g_s [ (size_t)M_ * H_ ];      // 1 MB
__device__ float g_am[ NBH * NC ];
__device__ float g_au[ NBH * NC ];
__device__ float g_aw[ NBH * NC * D_ ];
__device__ float g_pm[ NBH * NC ];
__device__ float g_pu[ NBH * NC ];
__device__ float g_pw[ NBH * NC * D_ ];

// ---------------- helpers ----------------
__device__ __forceinline__ void ldsm_x4(uint32_t* r, const void* p) {
    uint32_t a = (uint32_t)__cvta_generic_to_shared(p);
    asm volatile("ldmatrix.sync.aligned.m8n8.x4.shared.b16 {%0,%1,%2,%3}, [%4];"
                 : "=r"(r[0]), "=r"(r[1]), "=r"(r[2]), "=r"(r[3]) : "r"(a));
}
__device__ __forceinline__ void ldsm_x2t(uint32_t* r, const void* p) {
    uint32_t a = (uint32_t)__cvta_generic_to_shared(p);
    asm volatile("ldmatrix.sync.aligned.m8n8.x2.trans.shared.b16 {%0,%1}, [%2];"
                 : "=r"(r[0]), "=r"(r[1]) : "r"(a));
}
// fp16-accumulate MMA: D(f16x2 pair) = A*B + C
__device__ __forceinline__ void mma16816h(uint32_t* c, const uint32_t* a, const uint32_t* b) {
    asm volatile(
        "mma.sync.aligned.m16n8k16.row.col.f16.f16.f16.f16 "
        "{%0,%1}, {%2,%3,%4,%5}, {%6,%7}, {%0,%1};"
        : "+r"(c[0]), "+r"(c[1])
        : "r"(a[0]), "r"(a[1]), "r"(a[2]), "r"(a[3]), "r"(b[0]), "r"(b[1]));
}
__device__ __forceinline__ void cpa16(void* dst, const void* src) {
    uint32_t d = (uint32_t)__cvta_generic_to_shared(dst);
    asm volatile("cp.async.cg.shared.global [%0], [%1], 16;" :: "r"(d), "l"(src));
}
__device__ __forceinline__ uint32_t pack2h(__half a, __half b) {
    return (uint32_t)__half_as_ushort(a) | ((uint32_t)__half_as_ushort(b) << 16);
}

// ---------------------------------------------------------------------------
// Kernel 0: one-time fp32 -> fp16 convert of A and B.
// ---------------------------------------------------------------------------
#define NA4 ((size_t)M_ * I_ / 4)
#define NB4 ((size_t)I_ * NTOT / 4)
__global__ __launch_bounds__(256)
void k_split(const float* __restrict__ inp, const float* __restrict__ kvw)
{
    size_t i = (size_t)blockIdx.x * 256 + threadIdx.x;
    const float4* src;
    __half* dst;
    size_t o;
    if (i < NA4)            { src = (const float4*)inp; dst = g_a; o = i; }
    else if (i < NA4 + NB4) { src = (const float4*)kvw; dst = g_b; o = i - NA4; }
    else return;
    float4 x = src[o];
    ((uint2*)dst)[o] = make_uint2(
        pack2h(__float2half_rn(x.x), __float2half_rn(x.y)),
        pack2h(__float2half_rn(x.z), __float2half_rn(x.w)));
}

// ---------------------------------------------------------------------------
// Kernel 1: fp16 mma.sync GEMM (fp16 acc, K=64 group promotion to fp32)
//           + silu + score + v-store + fused per-chunk scan aggregates.
// Tile 128x256 (2 heads), 8 warps (2x4), KC=32, 4-stage cp.async ring.
// ---------------------------------------------------------------------------
struct GSmem {
    __half As[STG][128][40];   // 40960 B
    __half Bs[STG][KC][264];   // 67584 B
    float sred[2][128][2];
    float s_sh[2][128];
    float e_sh[2][128];
    float w_sh[2][2][64];
    float m_sh[2][2];
    float u_sh[2][2];
};

__global__ __launch_bounds__(256, 1)
void k_gemm_silu(const float* __restrict__ qw)
{
    extern __shared__ __align__(16) char smem_raw[];
    GSmem& S = *reinterpret_cast<GSmem*>(smem_raw);

    const int t    = threadIdx.x;
    const int warp = t >> 5, lane = t & 31;
    const int wm   = warp >> 2, wn = warp & 3;
    const int g    = lane >> 2, tg = lane & 3;
    const int m0   = blockIdx.x * 128;
    const int n0   = blockIdx.y * 256;

    float acc[4][8][4];         // fp32 master accumulators
    uint32_t hacc[4][8][2];     // fp16 group accumulators
#pragma unroll
    for (int i = 0; i < 4; i++)
#pragma unroll
        for (int j = 0; j < 8; j++) {
#pragma unroll
            for (int c = 0; c < 4; c++) acc[i][j][c] = 0.f;
            hacc[i][j][0] = 0u; hacc[i][j][1] = 0u;
        }

    auto load_stage = [&](int st, int bf) {
        const size_t k0 = (size_t)st * KC;
#pragma unroll
        for (int q = 0; q < 2; q++) {
            int i = t + q * 256;
            int row = i >> 2, c16 = i & 3;
            size_t gi = (size_t)(m0 + row) * I_ + k0 + c16 * 8;
            cpa16(&S.As[bf][row][c16 * 8], g_a + gi);
        }
#pragma unroll
        for (int q = 0; q < 4; q++) {
            int i = t + q * 256;
            int row = i >> 5, c16 = i & 31;
            size_t gi = (size_t)(k0 + row) * NTOT + n0 + c16 * 8;
            cpa16(&S.Bs[bf][row][c16 * 8], g_b + gi);
        }
        asm volatile("cp.async.commit_group;");
    };

    const int arow = lane & 15;
    const int acol = (lane >> 4) * 8;

    load_stage(0, 0);
    load_stage(1, 1);
    load_stage(2, 2);

#pragma unroll 1
    for (int s = 0; s < NST; s++) {
        const int buf = s & 3;
        if (s <= NST - 3)      asm volatile("cp.async.wait_group 2;");
        else if (s == NST - 2) asm volatile("cp.async.wait_group 1;");
        else                   asm volatile("cp.async.wait_group 0;");
        __syncthreads();
        if (s + 3 < NST) load_stage(s + 3, (s + 3) & 3);

#pragma unroll
        for (int ks = 0; ks < 2; ks++) {
            uint32_t af[4][4];
#pragma unroll
            for (int it = 0; it < 4; it++)
                ldsm_x4(af[it], &S.As[buf][wm * 64 + it * 16 + arow][ks * 16 + acol]);
#pragma unroll
            for (int jt = 0; jt < 8; jt++) {
                uint32_t bf2[2];
                ldsm_x2t(bf2, &S.Bs[buf][ks * 16 + arow][wn * 64 + jt * 8]);
#pragma unroll
                for (int it = 0; it < 4; it++)
                    mma16816h(hacc[it][jt], af[it], bf2);
            }
        }
        if (s & 1) {   // promote every 2 stages (K=64 per fp16 group)
#pragma unroll
            for (int it = 0; it < 4; it++)
#pragma unroll
                for (int jt = 0; jt < 8; jt++) {
                    float2 lo = __half22float2(*(__half2*)&hacc[it][jt][0]);
                    float2 hi = __half22float2(*(__half2*)&hacc[it][jt][1]);
                    acc[it][jt][0] += lo.x;
                    acc[it][jt][1] += lo.y;
                    acc[it][jt][2] += hi.x;
                    acc[it][jt][3] += hi.y;
                    hacc[it][jt][0] = 0u;
                    hacc[it][jt][1] = 0u;
                }
        }
    }
    __syncthreads();

    // ---- epilogue: silu, v store, score partials ----
#pragma unroll
    for (int it = 0; it < 4; it++)
#pragma unroll
        for (int jt = 0; jt < 8; jt++)
#pragma unroll
            for (int c = 0; c < 4; c++) {
                float x = acc[it][jt][c];
                acc[it][jt][c] = __fdividef(x, 1.f + __expf(-x));
            }

    const int head_l = wn >> 1;
    const int head_g = blockIdx.y * 2 + head_l;
    float ps[4][2];
#pragma unroll
    for (int it = 0; it < 4; it++) { ps[it][0] = 0.f; ps[it][1] = 0.f; }

#pragma unroll
    for (int it = 0; it < 4; it++) {
        const int row0 = m0 + wm * 64 + it * 16 + g;
#pragma unroll
        for (int jt = 0; jt < 8; jt++) {
            const int d  = (wn & 1) * 32 + jt * 4 + tg;
            const float qv = qw[head_g * D_ + d];
            ps[it][0] += qv * acc[it][jt][0];
            ps[it][1] += qv * acc[it][jt][2];
            g_v[((size_t)row0       * H_ + head_g) * D_ + d] = __float2half_rn(acc[it][jt][1]);
            g_v[((size_t)(row0 + 8) * H_ + head_g) * D_ + d] = __float2half_rn(acc[it][jt][3]);
        }
    }
#pragma unroll
    for (int it = 0; it < 4; it++)
#pragma unroll
        for (int hh = 0; hh < 2; hh++) {
            float v = ps[it][hh];
            v += __shfl_xor_sync(0xffffffffu, v, 1);
            v += __shfl_xor_sync(0xffffffffu, v, 2);
            ps[it][hh] = v;
        }
    if (tg == 0) {
#pragma unroll
        for (int it = 0; it < 4; it++) {
            S.sred[head_l][wm * 64 + it * 16 + g    ][wn & 1] = ps[it][0];
            S.sred[head_l][wm * 64 + it * 16 + g + 8][wn & 1] = ps[it][1];
        }
    }
    __syncthreads();

    // s per (head, row)
    {
        const int hl  = t >> 7;
        const int row = t & 127;
        float s = S.sred[hl][row][0] + S.sred[hl][row][1];
        g_s[(size_t)(m0 + row) * H_ + blockIdx.y * 2 + hl] = s;
        S.s_sh[hl][row] = s;
    }
    __syncthreads();

    // per-chunk (64-row half) max + expsum: warps 0,1 (one head each)
    if (warp < 2) {
#pragma unroll
        for (int half = 0; half < 2; half++) {
            float s0 = S.s_sh[warp][half * 64 + lane];
            float s1 = S.s_sh[warp][half * 64 + 32 + lane];
            float mx = fmaxf(s0, s1);
#pragma unroll
            for (int o = 16; o >= 1; o >>= 1)
                mx = fmaxf(mx, __shfl_xor_sync(0xffffffffu, mx, o));
            float e0 = __expf(s0 - mx);
            float e1 = __expf(s1 - mx);
            S.e_sh[warp][half * 64 + lane]      = e0;
            S.e_sh[warp][half * 64 + 32 + lane] = e1;
            float us = e0 + e1;
#pragma unroll
            for (int o = 16; o >= 1; o >>= 1)
                us += __shfl_xor_sync(0xffffffffu, us, o);
            if (lane == 0) { S.m_sh[warp][half] = mx; S.u_sh[warp][half] = us; }
        }
    }
    __syncthreads();

    // chunk w: each warp covers rows wm*64..+63 == chunk half wm
    {
        float pw[8];
#pragma unroll
        for (int jt = 0; jt < 8; jt++) pw[jt] = 0.f;
#pragma unroll
        for (int it = 0; it < 4; it++) {
            const int r0 = wm * 64 + it * 16 + g;
            float e0 = S.e_sh[head_l][r0];
            float e1 = S.e_sh[head_l][r0 + 8];
#pragma unroll
            for (int jt = 0; jt < 8; jt++)
                pw[jt] = fmaf(e0, acc[it][jt][1], fmaf(e1, acc[it][jt][3], pw[jt]));
        }
#pragma unroll
        for (int jt = 0; jt < 8; jt++) {
            float v = pw[jt];
            v += __shfl_xor_sync(0xffffffffu, v, 4);
            v += __shfl_xor_sync(0xffffffffu, v, 8);
            v += __shfl_xor_sync(0xffffffffu, v, 16);
            pw[jt] = v;
        }
        if (g == 0) {
#pragma unroll
            for (int jt = 0; jt < 8; jt++)
                S.w_sh[head_l][wm][(wn & 1) * 32 + jt * 4 + tg] = pw[jt];
        }
    }
    __syncthreads();

    // write chunk aggregates
    {
        const int hl   = t >> 7;
        const int half = (t >> 6) & 1;
        const int d    = t & 63;
        const int hg   = blockIdx.y * 2 + hl;
        const int b    = m0 >> 12;
        const int cb   = (m0 & 4095) >> 6;
        const int idx  = (b * H_ + hg) * NC + cb + half;
        g_aw[idx * D_ + d] = S.w_sh[hl][half][d];
        if (d == 0) { g_am[idx] = S.m_sh[hl][half]; g_au[idx] = S.u_sh[hl][half]; }
    }
}

// ---------------------------------------------------------------------------
// Kernel 3: exclusive prefix over chunk aggregates.
// ---------------------------------------------------------------------------
__global__ __launch_bounds__(64)
void k_prefix()
{
    const int bh = blockIdx.x;
    const int d  = threadIdx.x;
    float m = -1e30f, u = 0.f, w = 0.f;
    for (int c = 0; c < NC; c++) {
        const int idx = bh * NC + c;
        if (d == 0) { g_pm[idx] = m; g_pu[idx] = u; }
        g_pw[idx * D_ + d] = w;
        float am = g_am[idx];
        float au = g_au[idx];
        float aw = g_aw[idx * D_ + d];
        float mn = fmaxf(m, am);
        float ea = __expf(m  - mn);
        float eb = __expf(am - mn);
        u = u * ea + au * eb;
        w = w * ea + aw * eb;
        m = mn;
    }
}

// ---------------------------------------------------------------------------
// Kernel 4: apply — 4 heads per block (256 threads), CH=64, fp16 v.
// ---------------------------------------------------------------------------
__global__ __launch_bounds__(256)
void k_apply(float* __restrict__ out)
{
    const int c   = blockIdx.x;
    const int bh0 = blockIdx.y * 4;
    const int t   = threadIdx.x;
    const int hh  = t >> 6;
    const int d   = t & 63;
    const int bh  = bh0 + hh;
    const int b   = bh >> 4;
    const int h   = bh & 15;
    const int t0  = c * CH;

    __shared__ float ssh[4][CH];
    {
        const int i  = t >> 2;
        const int hx = t & 3;
        ssh[hx][i] = g_s[(size_t)(b * T_ + t0 + i) * H_ + ((bh0 + hx) & 15)];
    }
    __syncthreads();

    const int idx = bh * NC + c;
    float m = g_pm[idx];
    float u = g_pu[idx];
    float w = g_pw[idx * D_ + d];

    const __half* vp = g_v + ((size_t)(b * T_ + t0) * H_ + h) * D_ + d;
    float*        op = out + ((size_t)(b * T_ + t0) * H_ + h) * D_ + d;

#pragma unroll 4
    for (int i = 0; i < CH; i++) {
        float s  = ssh[hh][i];
        float mn = fmaxf(m, s);
        float ea = __expf(m - mn);
        float eb = __expf(s - mn);
        u = u * ea + eb;
        w = fmaf(w, ea, __half2float(vp[(size_t)i * (H_ * D_)]) * eb);
        m = mn;
        op[(size_t)i * (H_ * D_)] = __fdividef(w, u);
    }
}

// ---------------------------------------------------------------------------
extern "C" void kernel_launch(void* const* d_in, const int* in_sizes, int n_in,
                              void* d_out, int out_size)
{
    const float* inp = (const float*)d_in[0];   // (B,T,I)
    const float* kvw = (const float*)d_in[1];   // (I,H,D,2)
    const float* qw  = (const float*)d_in[2];   // (H,D)
    float* out = (float*)d_out;                 // (B,T,H,D)

    static int init = 0;
    if (!init) {
        cudaFuncSetAttribute(k_gemm_silu,
                             cudaFuncAttributeMaxDynamicSharedMemorySize,
                             (int)sizeof(GSmem));
        init = 1;
    }

    const int nsplit = (int)((NA4 + NB4 + 255) / 256);
    k_split<<<nsplit, 256>>>(inp, kvw);
    k_gemm_silu<<<dim3(M_ / 128, NTOT / 256), 256, sizeof(GSmem)>>>(qw);
    k_prefix<<<NBH, 64>>>();
    k_apply <<<dim3(NC, NBH / 4), 256>>>(out);
}

// round 12
// speedup vs baseline: 1.0689x; 1.0689x over previous
#include <cuda_runtime.h>
#include <cuda_fp16.h>
#include <cstdint>

#define B_   4
#define T_   4096
#define I_   1024
#define H_   16
#define D_   64
#define M_   (B_ * T_)        // 16384 rows (b,t)
#define NTOT 2048             // total N columns = H * 128
#define CH   64               // scan chunk length
#define NC   (T_ / CH)        // 64 chunks
#define NBH  (B_ * H_)        // 64 (b,h) pairs

#define KC   32               // K per pipeline stage
#define NST  (I_ / KC)        // 32 stages
#define STG  4                // ring depth

// ---------------- scratch (device globals: allocation-free) ----------------
__device__ __align__(16) __half g_a [(size_t)M_ * I_];   // 32 MB  A fp16
__device__ __align__(16) __half g_b [(size_t)I_ * NTOT]; // 4 MB   B [K][N] fp16
__device__ __align__(16) __half g_v [ (size_t)M_ * H_ * D_ ]; // 32 MB v fp16
__device__ __align__(16) float g_s [ (size_t)M_ * H_ ];      // 1 MB
__device__ float g_am[ NBH * NC ];
__device__ float g_au[ NBH * NC ];
__device__ float g_aw[ NBH * NC * D_ ];
__device__ float g_pm[ NBH * NC ];
__device__ float g_pu[ NBH * NC ];
__device__ float g_pw[ NBH * NC * D_ ];

// ---------------- helpers ----------------
__device__ __forceinline__ void ldsm_x4(uint32_t* r, const void* p) {
    uint32_t a = (uint32_t)__cvta_generic_to_shared(p);
    asm volatile("ldmatrix.sync.aligned.m8n8.x4.shared.b16 {%0,%1,%2,%3}, [%4];"
                 : "=r"(r[0]), "=r"(r[1]), "=r"(r[2]), "=r"(r[3]) : "r"(a));
}
__device__ __forceinline__ void ldsm_x2t(uint32_t* r, const void* p) {
    uint32_t a = (uint32_t)__cvta_generic_to_shared(p);
    asm volatile("ldmatrix.sync.aligned.m8n8.x2.trans.shared.b16 {%0,%1}, [%2];"
                 : "=r"(r[0]), "=r"(r[1]) : "r"(a));
}
__device__ __forceinline__ void mma16816(float* c, const uint32_t* a, const uint32_t* b) {
    asm volatile(
        "mma.sync.aligned.m16n8k16.row.col.f32.f16.f16.f32 "
        "{%0,%1,%2,%3}, {%4,%5,%6,%7}, {%8,%9}, {%0,%1,%2,%3};"
        : "+f"(c[0]), "+f"(c[1]), "+f"(c[2]), "+f"(c[3])
        : "r"(a[0]), "r"(a[1]), "r"(a[2]), "r"(a[3]), "r"(b[0]), "r"(b[1]));
}
__device__ __forceinline__ void cpa16(void* dst, const void* src) {
    uint32_t d = (uint32_t)__cvta_generic_to_shared(dst);
    asm volatile("cp.async.cg.shared.global [%0], [%1], 16;" :: "r"(d), "l"(src));
}
__device__ __forceinline__ uint32_t pack2h(__half a, __half b) {
    return (uint32_t)__half_as_ushort(a) | ((uint32_t)__half_as_ushort(b) << 16);
}

// ---------------------------------------------------------------------------
// Kernel 0: one-time fp32 -> fp16 convert of A and B.
// ---------------------------------------------------------------------------
#define NA4 ((size_t)M_ * I_ / 4)
#define NB4 ((size_t)I_ * NTOT / 4)
__global__ __launch_bounds__(256)
void k_split(const float* __restrict__ inp, const float* __restrict__ kvw)
{
    size_t i = (size_t)blockIdx.x * 256 + threadIdx.x;
    const float4* src;
    __half* dst;
    size_t o;
    if (i < NA4)            { src = (const float4*)inp; dst = g_a; o = i; }
    else if (i < NA4 + NB4) { src = (const float4*)kvw; dst = g_b; o = i - NA4; }
    else return;
    float4 x = src[o];
    ((uint2*)dst)[o] = make_uint2(
        pack2h(__float2half_rn(x.x), __float2half_rn(x.y)),
        pack2h(__float2half_rn(x.z), __float2half_rn(x.w)));
}

// ---------------------------------------------------------------------------
// Kernel 1: fp16 mma.sync GEMM (1-pass, fp32 acc) + silu + score + v-store
//           + fused per-chunk scan aggregates.
// Tile 128x256 (2 heads), 8 warps (2x4), KC=32, 4-stage cp.async ring.
// ---------------------------------------------------------------------------
struct GSmem {
    __half As[STG][128][40];   // 40960 B
    __half Bs[STG][KC][264];   // 67584 B
    float sred[2][128][2];
    float s_sh[2][128];
    float e_sh[2][128];
    float w_sh[2][2][64];
    float m_sh[2][2];
    float u_sh[2][2];
};

__global__ __launch_bounds__(256, 1)
void k_gemm_silu(const float* __restrict__ qw)
{
    extern __shared__ __align__(16) char smem_raw[];
    GSmem& S = *reinterpret_cast<GSmem*>(smem_raw);

    const int t    = threadIdx.x;
    const int warp = t >> 5, lane = t & 31;
    const int wm   = warp >> 2, wn = warp & 3;
    const int g    = lane >> 2, tg = lane & 3;
    const int m0   = blockIdx.x * 128;
    const int n0   = blockIdx.y * 256;

    float acc[4][8][4];
#pragma unroll
    for (int i = 0; i < 4; i++)
#pragma unroll
        for (int j = 0; j < 8; j++)
#pragma unroll
            for (int c = 0; c < 4; c++) acc[i][j][c] = 0.f;

    auto load_stage = [&](int st, int bf) {
        const size_t k0 = (size_t)st * KC;
#pragma unroll
        for (int q = 0; q < 2; q++) {
            int i = t + q * 256;
            int row = i >> 2, c16 = i & 3;
            size_t gi = (size_t)(m0 + row) * I_ + k0 + c16 * 8;
            cpa16(&S.As[bf][row][c16 * 8], g_a + gi);
        }
#pragma unroll
        for (int q = 0; q < 4; q++) {
            int i = t + q * 256;
            int row = i >> 5, c16 = i & 31;
            size_t gi = (size_t)(k0 + row) * NTOT + n0 + c16 * 8;
            cpa16(&S.Bs[bf][row][c16 * 8], g_b + gi);
        }
        asm volatile("cp.async.commit_group;");
    };

    const int arow = lane & 15;
    const int acol = (lane >> 4) * 8;

    load_stage(0, 0);
    load_stage(1, 1);
    load_stage(2, 2);

#pragma unroll 1
    for (int s = 0; s < NST; s++) {
        const int buf = s & 3;
        if (s <= NST - 3)      asm volatile("cp.async.wait_group 2;");
        else if (s == NST - 2) asm volatile("cp.async.wait_group 1;");
        else                   asm volatile("cp.async.wait_group 0;");
        __syncthreads();
        if (s + 3 < NST) load_stage(s + 3, (s + 3) & 3);

#pragma unroll
        for (int ks = 0; ks < 2; ks++) {
            uint32_t af[4][4];
#pragma unroll
            for (int it = 0; it < 4; it++)
                ldsm_x4(af[it], &S.As[buf][wm * 64 + it * 16 + arow][ks * 16 + acol]);
#pragma unroll
            for (int jt = 0; jt < 8; jt++) {
                uint32_t bf2[2];
                ldsm_x2t(bf2, &S.Bs[buf][ks * 16 + arow][wn * 64 + jt * 8]);
#pragma unroll
                for (int it = 0; it < 4; it++)
                    mma16816(acc[it][jt], af[it], bf2);
            }
        }
    }
    __syncthreads();

    // ---- epilogue: silu, v store (fp16), score partials ----
#pragma unroll
    for (int it = 0; it < 4; it++)
#pragma unroll
        for (int jt = 0; jt < 8; jt++)
#pragma unroll
            for (int c = 0; c < 4; c++) {
                float x = acc[it][jt][c];
                acc[it][jt][c] = __fdividef(x, 1.f + __expf(-x));
            }

    const int head_l = wn >> 1;
    const int head_g = blockIdx.y * 2 + head_l;
    float ps[4][2];
#pragma unroll
    for (int it = 0; it < 4; it++) { ps[it][0] = 0.f; ps[it][1] = 0.f; }

#pragma unroll
    for (int it = 0; it < 4; it++) {
        const int row0 = m0 + wm * 64 + it * 16 + g;
#pragma unroll
        for (int jt = 0; jt < 8; jt++) {
            const int d  = (wn & 1) * 32 + jt * 4 + tg;
            const float qv = qw[head_g * D_ + d];
            ps[it][0] += qv * acc[it][jt][0];
            ps[it][1] += qv * acc[it][jt][2];
            g_v[((size_t)row0       * H_ + head_g) * D_ + d] = __float2half_rn(acc[it][jt][1]);
            g_v[((size_t)(row0 + 8) * H_ + head_g) * D_ + d] = __float2half_rn(acc[it][jt][3]);
        }
    }
#pragma unroll
    for (int it = 0; it < 4; it++)
#pragma unroll
        for (int hh = 0; hh < 2; hh++) {
            float v = ps[it][hh];
            v += __shfl_xor_sync(0xffffffffu, v, 1);
            v += __shfl_xor_sync(0xffffffffu, v, 2);
            ps[it][hh] = v;
        }
    if (tg == 0) {
#pragma unroll
        for (int it = 0; it < 4; it++) {
            S.sred[head_l][wm * 64 + it * 16 + g    ][wn & 1] = ps[it][0];
            S.sred[head_l][wm * 64 + it * 16 + g + 8][wn & 1] = ps[it][1];
        }
    }
    __syncthreads();

    // s per (head, row)
    {
        const int hl  = t >> 7;
        const int row = t & 127;
        float s = S.sred[hl][row][0] + S.sred[hl][row][1];
        g_s[(size_t)(m0 + row) * H_ + blockIdx.y * 2 + hl] = s;
        S.s_sh[hl][row] = s;
    }
    __syncthreads();

    // per-chunk (64-row half) max + expsum: warps 0,1 (one head each)
    if (warp < 2) {
#pragma unroll
        for (int half = 0; half < 2; half++) {
            float s0 = S.s_sh[warp][half * 64 + lane];
            float s1 = S.s_sh[warp][half * 64 + 32 + lane];
            float mx = fmaxf(s0, s1);
#pragma unroll
            for (int o = 16; o >= 1; o >>= 1)
                mx = fmaxf(mx, __shfl_xor_sync(0xffffffffu, mx, o));
            float e0 = __expf(s0 - mx);
            float e1 = __expf(s1 - mx);
            S.e_sh[warp][half * 64 + lane]      = e0;
            S.e_sh[warp][half * 64 + 32 + lane] = e1;
            float us = e0 + e1;
#pragma unroll
            for (int o = 16; o >= 1; o >>= 1)
                us += __shfl_xor_sync(0xffffffffu, us, o);
            if (lane == 0) { S.m_sh[warp][half] = mx; S.u_sh[warp][half] = us; }
        }
    }
    __syncthreads();

    // chunk w: each warp covers rows wm*64..+63 == chunk half wm
    {
        float pw[8];
#pragma unroll
        for (int jt = 0; jt < 8; jt++) pw[jt] = 0.f;
#pragma unroll
        for (int it = 0; it < 4; it++) {
            const int r0 = wm * 64 + it * 16 + g;
            float e0 = S.e_sh[head_l][r0];
            float e1 = S.e_sh[head_l][r0 + 8];
#pragma unroll
            for (int jt = 0; jt < 8; jt++)
                pw[jt] = fmaf(e0, acc[it][jt][1], fmaf(e1, acc[it][jt][3], pw[jt]));
        }
#pragma unroll
        for (int jt = 0; jt < 8; jt++) {
            float v = pw[jt];
            v += __shfl_xor_sync(0xffffffffu, v, 4);
            v += __shfl_xor_sync(0xffffffffu, v, 8);
            v += __shfl_xor_sync(0xffffffffu, v, 16);
            pw[jt] = v;
        }
        if (g == 0) {
#pragma unroll
            for (int jt = 0; jt < 8; jt++)
                S.w_sh[head_l][wm][(wn & 1) * 32 + jt * 4 + tg] = pw[jt];
        }
    }
    __syncthreads();

    // write chunk aggregates
    {
        const int hl   = t >> 7;
        const int half = (t >> 6) & 1;
        const int d    = t & 63;
        const int hg   = blockIdx.y * 2 + hl;
        const int b    = m0 >> 12;
        const int cb   = (m0 & 4095) >> 6;
        const int idx  = (b * H_ + hg) * NC + cb + half;
        g_aw[idx * D_ + d] = S.w_sh[hl][half][d];
        if (d == 0) { g_am[idx] = S.m_sh[hl][half]; g_au[idx] = S.u_sh[hl][half]; }
    }
}

// ---------------------------------------------------------------------------
// Kernel 3: exclusive prefix over chunk aggregates.
// ---------------------------------------------------------------------------
__global__ __launch_bounds__(64)
void k_prefix()
{
    const int bh = blockIdx.x;
    const int d  = threadIdx.x;
    float m = -1e30f, u = 0.f, w = 0.f;
    for (int c = 0; c < NC; c++) {
        const int idx = bh * NC + c;
        if (d == 0) { g_pm[idx] = m; g_pu[idx] = u; }
        g_pw[idx * D_ + d] = w;
        float am = g_am[idx];
        float au = g_au[idx];
        float aw = g_aw[idx * D_ + d];
        float mn = fmaxf(m, am);
        float ea = __expf(m  - mn);
        float eb = __expf(am - mn);
        u = u * ea + au * eb;
        w = w * ea + aw * eb;
        m = mn;
    }
}

// ---------------------------------------------------------------------------
// Kernel 4: apply — 2 d-lanes/thread, 8 heads/block (256 thr), CH=64, fp16 v.
// ---------------------------------------------------------------------------
__global__ __launch_bounds__(256)
void k_apply(float* __restrict__ out)
{
    const int c    = blockIdx.x;
    const int bh0  = blockIdx.y * 8;
    const int t    = threadIdx.x;
    const int hh   = t >> 5;            // 0..7 (bh within block)
    const int lane = t & 31;            // d pair index: d = 2*lane
    const int bh   = bh0 + hh;
    const int b    = bh >> 4;
    const int h    = bh & 15;
    const int t0   = c * CH;

    __shared__ float ssh[8][CH];
#pragma unroll
    for (int q = 0; q < 2; q++) {
        const int idx = t + q * 256;
        const int hx  = idx >> 6;
        const int i   = idx & 63;
        const int bhx = bh0 + hx;
        ssh[hx][i] = g_s[(size_t)((bhx >> 4) * T_ + t0 + i) * H_ + (bhx & 15)];
    }
    __syncthreads();

    const int idx = bh * NC + c;
    float m = g_pm[idx];
    float u = g_pu[idx];
    float2 wv = *(const float2*)&g_pw[idx * D_ + 2 * lane];
    float w0 = wv.x, w1 = wv.y;

    const __half2* vp = (const __half2*)(g_v + ((size_t)(b * T_ + t0) * H_ + h) * D_ + 2 * lane);
    float2*        op = (float2*)(out + ((size_t)(b * T_ + t0) * H_ + h) * D_ + 2 * lane);
    const int      st = (H_ * D_) / 2;  // half2 stride per timestep

#pragma unroll 4
    for (int i = 0; i < CH; i++) {
        float s  = ssh[hh][i];
        float mn = fmaxf(m, s);
        float ea = __expf(m - mn);
        float eb = __expf(s - mn);
        u = u * ea + eb;
        float2 v2 = __half22float2(vp[(size_t)i * st]);
        w0 = fmaf(w0, ea, v2.x * eb);
        w1 = fmaf(w1, ea, v2.y * eb);
        m = mn;
        float r = __fdividef(1.f, u);
        op[(size_t)i * st] = make_float2(w0 * r, w1 * r);
    }
}

// ---------------------------------------------------------------------------
extern "C" void kernel_launch(void* const* d_in, const int* in_sizes, int n_in,
                              void* d_out, int out_size)
{
    const float* inp = (const float*)d_in[0];   // (B,T,I)
    const float* kvw = (const float*)d_in[1];   // (I,H,D,2)
    const float* qw  = (const float*)d_in[2];   // (H,D)
    float* out = (float*)d_out;                 // (B,T,H,D)

    static int init = 0;
    if (!init) {
        cudaFuncSetAttribute(k_gemm_silu,
                             cudaFuncAttributeMaxDynamicSharedMemorySize,
                             (int)sizeof(GSmem));
        init = 1;
    }

    const int nsplit = (int)((NA4 + NB4 + 255) / 256);
    k_split<<<nsplit, 256>>>(inp, kvw);
    k_gemm_silu<<<dim3(M_ / 128, NTOT / 256), 256, sizeof(GSmem)>>>(qw);
    k_prefix<<<NBH, 64>>>();
    k_apply <<<dim3(NC, NBH / 8), 256>>>(out);
}